// round 15
// baseline (speedup 1.0000x reference)
#include <cuda_runtime.h>
#include <cuda_fp16.h>
#include <stdint.h>

#define TOKENS 8192
#define IN_F   4096
#define OUT_F  11008

// ---------------- scratch (device globals; no allocation allowed) -----------
__device__ __align__(16) float  g_sa[IN_F];
__device__ __align__(16) float  g_rsa[IN_F];
__device__ __align__(16) __half g_xdeq[(size_t)TOKENS * IN_F];   // 64 MB
__device__ __align__(16) __half g_wdeq[(size_t)OUT_F  * IN_F];   // 88 MB
__device__ int g_sw_mode;
__device__ int g_pw_is_i32;

// ============================================================================
// Kernel 0: input dtype detection
// ============================================================================
__global__ void detect_kernel(const void* __restrict__ s_w, const void* __restrict__ pw) {
    bool bf_ok = true;
    const uint16_t* u16 = (const uint16_t*)s_w;
#pragma unroll
    for (int i = 0; i < 16; ++i) {
        float v = __uint_as_float(((uint32_t)u16[i]) << 16);
        bf_ok = bf_ok && isfinite(v) && (v > 1e-4f) && (v < 0.5f);
    }
    bool f32_ok = true;
    const float* f = (const float*)s_w;
#pragma unroll
    for (int i = 0; i < 8; ++i) {
        float v = f[i];
        f32_ok = f32_ok && isfinite(v) && (v > 1e-4f) && (v < 0.5f);
    }
    g_sw_mode = bf_ok ? 2 : (f32_ok ? 1 : 0);

    const int* pi = (const int*)pw;
    bool i32_ok = true;
#pragma unroll
    for (int i = 0; i < 64; ++i) { int v = pi[i]; i32_ok = i32_ok && (v >= 0) && (v <= 255); }
    g_pw_is_i32 = i32_ok ? 1 : 0;
}

// ============================================================================
// Kernel 1: per-column 0.999 quantile of |x| -> s_a (and 1/s_a)
// ============================================================================
__global__ void quantile_kernel(const float* __restrict__ x) {
    __shared__ float tops[256][10];
    const int t = threadIdx.x, cl = t & 63, chunk = t >> 6;
    const int col = blockIdx.x * 64 + cl;
    const float* p = x + (size_t)chunk * 2048 * IN_F + col;

    float tt[10];
#pragma unroll
    for (int i = 0; i < 10; ++i) tt[i] = -1.0f;
#pragma unroll 4
    for (int r = 0; r < 2048; ++r) {
        float v = fabsf(p[(size_t)r * IN_F]);
        if (v > tt[9]) {
            tt[9] = v;
#pragma unroll
            for (int j = 9; j > 0; --j)
                if (tt[j] > tt[j - 1]) { float tmp = tt[j - 1]; tt[j - 1] = tt[j]; tt[j] = tmp; }
        }
    }
#pragma unroll
    for (int i = 0; i < 10; ++i) tops[t][i] = tt[i];
    __syncthreads();

    if (chunk == 0) {
        int pi[4] = {0, 0, 0, 0};
        float v9th = 0.f, v10th = 0.f;
        for (int i = 0; i < 10; ++i) {
            int best = 0; float bv = tops[cl][pi[0]];
#pragma unroll
            for (int j = 1; j < 4; ++j) {
                float c = tops[cl + 64 * j][pi[j]];
                if (c > bv) { bv = c; best = j; }
            }
            pi[best]++;
            if (i == 8) v9th = bv;
            if (i == 9) v10th = bv;
        }
        float pos = 0.999f * 8191.0f;
        float qv  = v10th * (8183.0f - pos) + v9th * (pos - 8182.0f);
        float s = fmaxf(qv, 1e-6f) / 127.0f;
        s = fmaxf(s, 1e-6f);
        s = __half2float(__float2half_rn(s));
        g_sa[col]  = s;
        g_rsa[col] = 1.0f / s;
    }
}

// ============================================================================
// Kernel 2: fake-quant x -> fp16 x_deq (8 elem/thread, reciprocal multiply)
// ============================================================================
__global__ void quant_x_kernel(const float* __restrict__ x) {
    size_t i = (size_t)blockIdx.x * blockDim.x + threadIdx.x;
    size_t base = i * 8;
    int kb = (int)(base & (IN_F - 1));

    const float4* xp = (const float4*)(x + base);
    float4 x0 = xp[0], x1 = xp[1];
    const float4* sp = (const float4*)(g_sa + kb);
    float4 s0 = sp[0], s1 = sp[1];
    const float4* rp = (const float4*)(g_rsa + kb);
    float4 r0 = rp[0], r1 = rp[1];

    float xs[8] = {x0.x, x0.y, x0.z, x0.w, x1.x, x1.y, x1.z, x1.w};
    float ss[8] = {s0.x, s0.y, s0.z, s0.w, s1.x, s1.y, s1.z, s1.w};
    float rs[8] = {r0.x, r0.y, r0.z, r0.w, r1.x, r1.y, r1.z, r1.w};

    union { __half2 h2[4]; uint4 u; } pk;
#pragma unroll
    for (int j = 0; j < 8; j += 2) {
        float q0 = fminf(fmaxf(rintf(xs[j]     * rs[j]),     -127.f), 127.f);
        float q1 = fminf(fmaxf(rintf(xs[j + 1] * rs[j + 1]), -127.f), 127.f);
        pk.h2[j >> 1] = __halves2half2(__float2half_rn(q0 * ss[j]),
                                       __float2half_rn(q1 * ss[j + 1]));
    }
    reinterpret_cast<uint4*>(g_xdeq)[i] = pk.u;
}

// ============================================================================
// Kernel 3: int4 unpack + scale -> fp16 w_deq (8 packed bytes/thread)
// ============================================================================
__global__ void dequant_w_kernel(const void* __restrict__ pw,
                                 const void* __restrict__ s_w) {
    size_t i = (size_t)blockIdx.x * blockDim.x + threadIdx.x;
    int b8[8];
    if (g_pw_is_i32) {
        const int4* p = (const int4*)pw + i * 2;
        int4 a = p[0], b = p[1];
        b8[0] = a.x & 0xFF; b8[1] = a.y & 0xFF; b8[2] = a.z & 0xFF; b8[3] = a.w & 0xFF;
        b8[4] = b.x & 0xFF; b8[5] = b.y & 0xFF; b8[6] = b.z & 0xFF; b8[7] = b.w & 0xFF;
    } else {
        uint2 w = reinterpret_cast<const uint2*>(pw)[i];
#pragma unroll
        for (int j = 0; j < 4; ++j) { b8[j] = (w.x >> (8 * j)) & 0xFF; b8[4 + j] = (w.y >> (8 * j)) & 0xFF; }
    }
    int o = (int)(i >> 8);
    float sw;
    int mode = g_sw_mode;
    if (mode == 1)      sw = ((const float*)s_w)[o];
    else if (mode == 2) sw = __uint_as_float(((uint32_t)((const uint16_t*)s_w)[o]) << 16);
    else                sw = __half2float(((const __half*)s_w)[o]);

    union { __half2 h2[8]; uint4 u[2]; } pk;
#pragma unroll
    for (int j = 0; j < 8; ++j) {
        int b  = b8[j];
        int lo = ((b & 15) ^ 8) - 8;
        int hi = ((b >> 4) ^ 8) - 8;
        pk.h2[j] = __halves2half2(__float2half_rn((float)lo * sw),
                                  __float2half_rn((float)hi * sw));
    }
    uint4* dst = reinterpret_cast<uint4*>(g_wdeq) + i * 2;
    dst[0] = pk.u[0];
    dst[1] = pk.u[1];
}

// ============================================================================
// Kernel 4: HYBRID GEMM  out = x_deq @ w_deq^T + bias
//   512 threads. Warps 8-15: R3 HMMA loop over K-chunks [0,114).
//   Warps 0-7: fp32 FFMA GEMM over K-chunks [114,128), own f32 smem tiles.
//   Each FFMA thread stages 16 halves of its row (TWO uint4 loads — a uint4
//   is 8 halves; round-13 bug was treating it as 16).
// ============================================================================
#define GBM 128
#define GBN 128
#define GBK 32
#define GST 40
#define CH_TOT 128
#define CH_FF  14
#define CH_MM  (CH_TOT - CH_FF)     // 114

// dynamic smem layout (bytes):
#define OFF_AS  0                    // mma A: 2 bufs x 128*40 halves = 20480
#define OFF_BS  20480                // mma B: 20480
#define OFF_AF  40960                // FFMA A: 32 x 132 floats = 16896
#define OFF_BF  57856                // FFMA B: 16896
#define SMEM_TOT 74752
#define PF_STRIDE 132                // merge buffer stride (floats) = 528 B, 16-aligned

extern __shared__ __align__(16) uint8_t dsm[];

__global__ void __launch_bounds__(512, 1)
gemm_kernel(const float* __restrict__ bias, float* __restrict__ out) {
    const int tid = threadIdx.x;
    const int wid = tid >> 5;
    const int bn = blockIdx.x, bm = blockIdx.y;

    float    facc[8][8];                 // FFMA accumulators (warps 0-7)
    float    macc[4][4][4];              // HMMA accumulators (warps 8-15)

    if (wid < 8) {
        // =================== FFMA group (256 threads) =====================
        const int ft = tid;
        const int tx = ft & 15, ty = ft >> 4;
        const int mrow = ft >> 1, kh = (ft & 1) * 16;   // 16 halves per thread
        const __half* Ag = g_xdeq + (size_t)(bm * GBM + mrow) * IN_F;
        const __half* Bg = g_wdeq + (size_t)(bn * GBN + mrow) * IN_F;
        float* Af = (float*)(dsm + OFF_AF);
        float* Bf = (float*)(dsm + OFF_BF);

#pragma unroll
        for (int mi = 0; mi < 8; ++mi)
#pragma unroll
            for (int ni = 0; ni < 8; ++ni) facc[mi][ni] = 0.f;

        uint4 aR0 = *(const uint4*)(Ag + CH_MM * GBK + kh);
        uint4 aR1 = *(const uint4*)(Ag + CH_MM * GBK + kh + 8);
        uint4 bR0 = *(const uint4*)(Bg + CH_MM * GBK + kh);
        uint4 bR1 = *(const uint4*)(Bg + CH_MM * GBK + kh + 8);

        for (int c = CH_MM; c < CH_TOT; ++c) {
            uint4 aN0 = make_uint4(0,0,0,0), aN1 = aN0, bN0 = aN0, bN1 = aN0;
            if (c + 1 < CH_TOT) {
                aN0 = *(const uint4*)(Ag + (size_t)(c + 1) * GBK + kh);
                aN1 = *(const uint4*)(Ag + (size_t)(c + 1) * GBK + kh + 8);
                bN0 = *(const uint4*)(Bg + (size_t)(c + 1) * GBK + kh);
                bN1 = *(const uint4*)(Bg + (size_t)(c + 1) * GBK + kh + 8);
            }
            asm volatile("bar.sync 2, 256;" ::: "memory");   // smem free
            {
                const __half* a0 = (const __half*)&aR0;
                const __half* a1 = (const __half*)&aR1;
                const __half* b0 = (const __half*)&bR0;
                const __half* b1 = (const __half*)&bR1;
#pragma unroll
                for (int j = 0; j < 8; ++j) {
                    Af[(kh + j)     * 132 + mrow] = __half2float(a0[j]);
                    Af[(kh + 8 + j) * 132 + mrow] = __half2float(a1[j]);
                    Bf[(kh + j)     * 132 + mrow] = __half2float(b0[j]);
                    Bf[(kh + 8 + j) * 132 + mrow] = __half2float(b1[j]);
                }
            }
            asm volatile("bar.sync 2, 256;" ::: "memory");   // smem ready
#pragma unroll 2
            for (int k = 0; k < GBK; ++k) {
                float4 a0 = *(const float4*)(Af + k * 132 + ty * 8);
                float4 a1 = *(const float4*)(Af + k * 132 + ty * 8 + 4);
                float4 b0 = *(const float4*)(Bf + k * 132 + tx * 8);
                float4 b1 = *(const float4*)(Bf + k * 132 + tx * 8 + 4);
                float av[8] = {a0.x, a0.y, a0.z, a0.w, a1.x, a1.y, a1.z, a1.w};
                float bv[8] = {b0.x, b0.y, b0.z, b0.w, b1.x, b1.y, b1.z, b1.w};
#pragma unroll
                for (int mi = 0; mi < 8; ++mi)
#pragma unroll
                    for (int ni = 0; ni < 8; ++ni)
                        facc[mi][ni] += av[mi] * bv[ni];
            }
            aR0 = aN0; aR1 = aN1; bR0 = bN0; bR1 = bN1;
        }
    } else {
        // =================== HMMA group (R3 loop, 256 threads) ============
        const int tid2 = tid - 256;
        const int warp = wid - 8, lane = tid & 31;
        const int wm = warp >> 2, wn = warp & 3;
        const __half* Ag = g_xdeq + (size_t)(bm * GBM) * IN_F;
        const __half* Bg = g_wdeq + (size_t)(bn * GBN) * IN_F;
        const uint32_t as_base = (uint32_t)__cvta_generic_to_shared(dsm + OFF_AS);
        const uint32_t bs_base = (uint32_t)__cvta_generic_to_shared(dsm + OFF_BS);

#pragma unroll
        for (int mt = 0; mt < 4; ++mt)
#pragma unroll
            for (int nt = 0; nt < 4; ++nt)
#pragma unroll
                for (int r = 0; r < 4; ++r) macc[mt][nt][r] = 0.f;

        auto load_tile = [&](int kt, int buf) {
#pragma unroll
            for (int h = 0; h < 2; ++h) {
                int c    = tid2 + h * 256;
                int row  = c >> 2;
                int col8 = (c & 3) * 8;
                const __half* ga = Ag + (size_t)row * IN_F + kt * GBK + col8;
                uint32_t sa = as_base + (uint32_t)(buf * GBM * GST + row * GST + col8) * 2u;
                asm volatile("cp.async.cg.shared.global [%0], [%1], 16;\n" :: "r"(sa), "l"(ga));
                const __half* gb = Bg + (size_t)row * IN_F + kt * GBK + col8;
                uint32_t sb = bs_base + (uint32_t)(buf * GBN * GST + row * GST + col8) * 2u;
                asm volatile("cp.async.cg.shared.global [%0], [%1], 16;\n" :: "r"(sb), "l"(gb));
            }
        };

        auto compute = [&](int buf) {
            const int g   = lane >> 3;
            const int idx = lane & 7;
#pragma unroll
            for (int kk = 0; kk < GBK; kk += 16) {
                uint32_t a[4][4];
#pragma unroll
                for (int mt = 0; mt < 4; ++mt) {
                    int row = wm * 64 + mt * 16 + idx + (g & 1) * 8;
                    int col = kk + (g >> 1) * 8;
                    uint32_t addr = as_base + (uint32_t)(buf * GBM * GST + row * GST + col) * 2u;
                    asm volatile("ldmatrix.sync.aligned.m8n8.x4.shared.b16 {%0,%1,%2,%3}, [%4];\n"
                                 : "=r"(a[mt][0]), "=r"(a[mt][1]), "=r"(a[mt][2]), "=r"(a[mt][3])
                                 : "r"(addr));
                }
                uint32_t b[2][4];
#pragma unroll
                for (int bt = 0; bt < 2; ++bt) {
                    int n   = wn * 32 + bt * 16 + idx + (g >> 1) * 8;
                    int col = kk + (g & 1) * 8;
                    uint32_t addr = bs_base + (uint32_t)(buf * GBN * GST + n * GST + col) * 2u;
                    asm volatile("ldmatrix.sync.aligned.m8n8.x4.shared.b16 {%0,%1,%2,%3}, [%4];\n"
                                 : "=r"(b[bt][0]), "=r"(b[bt][1]), "=r"(b[bt][2]), "=r"(b[bt][3])
                                 : "r"(addr));
                }
#pragma unroll
                for (int mt = 0; mt < 4; ++mt) {
#pragma unroll
                    for (int nt = 0; nt < 4; ++nt) {
                        uint32_t b0 = b[nt >> 1][(nt & 1) * 2];
                        uint32_t b1 = b[nt >> 1][(nt & 1) * 2 + 1];
                        asm volatile(
                            "mma.sync.aligned.m16n8k16.row.col.f32.f16.f16.f32 "
                            "{%0,%1,%2,%3}, {%4,%5,%6,%7}, {%8,%9}, {%0,%1,%2,%3};\n"
                            : "+f"(macc[mt][nt][0]), "+f"(macc[mt][nt][1]),
                              "+f"(macc[mt][nt][2]), "+f"(macc[mt][nt][3])
                            : "r"(a[mt][0]), "r"(a[mt][1]), "r"(a[mt][2]), "r"(a[mt][3]),
                              "r"(b0), "r"(b1));
                    }
                }
            }
        };

        load_tile(0, 0);
        asm volatile("cp.async.commit_group;\n");
        asm volatile("cp.async.wait_group 0;\n");
        asm volatile("bar.sync 1, 256;" ::: "memory");

        for (int kt = 0; kt < CH_MM; ++kt) {
            int cur = kt & 1;
            if (kt + 1 < CH_MM) {
                load_tile(kt + 1, cur ^ 1);
                asm volatile("cp.async.commit_group;\n");
            }
            compute(cur);
            if (kt + 1 < CH_MM) asm volatile("cp.async.wait_group 0;\n");
            asm volatile("bar.sync 1, 256;" ::: "memory");
        }
    }

    // =================== merge + epilogue ===================
    __syncthreads();                                  // both groups done
    if (wid < 8) {
        const int tx = tid & 15, ty = tid >> 4;
        float* Pf = (float*)dsm;
#pragma unroll
        for (int mi = 0; mi < 8; ++mi) {
            float* pr = Pf + (ty * 8 + mi) * PF_STRIDE + tx * 8;
#pragma unroll
            for (int ni = 0; ni < 8; ni += 4)
                *(float4*)(pr + ni) = make_float4(facc[mi][ni], facc[mi][ni + 1],
                                                  facc[mi][ni + 2], facc[mi][ni + 3]);
        }
    }
    __syncthreads();
    if (wid >= 8) {
        const int warp = wid - 8, lane = tid & 31;
        const int wm = warp >> 2, wn = warp & 3;
        const float* Pf = (const float*)dsm;
#pragma unroll
        for (int nt = 0; nt < 4; ++nt) {
            int cl = wn * 32 + nt * 8 + (lane & 3) * 2;
            int c0 = bn * GBN + cl;
            float b0 = bias[c0], b1 = bias[c0 + 1];
#pragma unroll
            for (int mt = 0; mt < 4; ++mt) {
                int rl = wm * 64 + mt * 16 + (lane >> 2);
                int r0 = bm * GBM + rl;
                float p00 = Pf[rl * PF_STRIDE + cl],       p01 = Pf[rl * PF_STRIDE + cl + 1];
                float p10 = Pf[(rl + 8) * PF_STRIDE + cl], p11 = Pf[(rl + 8) * PF_STRIDE + cl + 1];
                float2 v0 = make_float2(macc[mt][nt][0] + p00 + b0, macc[mt][nt][1] + p01 + b1);
                float2 v1 = make_float2(macc[mt][nt][2] + p10 + b0, macc[mt][nt][3] + p11 + b1);
                *reinterpret_cast<float2*>(out + (size_t)r0 * OUT_F + c0)       = v0;
                *reinterpret_cast<float2*>(out + (size_t)(r0 + 8) * OUT_F + c0) = v1;
            }
        }
    }
}

// ============================================================================
// launch
// ============================================================================
extern "C" void kernel_launch(void* const* d_in, const int* in_sizes, int n_in,
                              void* d_out, int out_size) {
    const float* x    = (const float*)d_in[0];
    const void*  pw   = (const void*)d_in[1];
    const void*  s_w  = (const void*)d_in[2];
    const float* bias = (const float*)d_in[3];
    float*       out  = (float*)d_out;

    static int smem_set = 0;
    if (!smem_set) {
        cudaFuncSetAttribute(gemm_kernel, cudaFuncAttributeMaxDynamicSharedMemorySize, SMEM_TOT);
        smem_set = 1;
    }

    detect_kernel<<<1, 1>>>(s_w, pw);
    quantile_kernel<<<IN_F / 64, 256>>>(x);
    quant_x_kernel<<<(TOKENS * IN_F / 8) / 256, 256>>>(x);
    dequant_w_kernel<<<(OUT_F * (IN_F / 2) / 8) / 256, 256>>>(pw, s_w);
    gemm_kernel<<<dim3(OUT_F / GBN, TOKENS / GBM), 512, SMEM_TOT>>>(bias, out);
}

// round 16
// speedup vs baseline: 1.5794x; 1.5794x over previous
#include <cuda_runtime.h>
#include <cuda_fp16.h>
#include <stdint.h>

#define TOKENS 8192
#define IN_F   4096
#define OUT_F  11008

// ---------------- scratch (device globals; no allocation allowed) -----------
__device__ __align__(16) float  g_sa[IN_F];
__device__ __align__(16) float  g_rsa[IN_F];
__device__ __align__(16) __half g_xdeq[(size_t)TOKENS * IN_F];   // 64 MB
__device__ __align__(16) __half g_wdeq[(size_t)OUT_F  * IN_F];   // 88 MB
__device__ int g_sw_mode;
__device__ int g_pw_is_i32;

// ============================================================================
// Kernel 0: input dtype detection
// ============================================================================
__global__ void detect_kernel(const void* __restrict__ s_w, const void* __restrict__ pw) {
    bool bf_ok = true;
    const uint16_t* u16 = (const uint16_t*)s_w;
#pragma unroll
    for (int i = 0; i < 16; ++i) {
        float v = __uint_as_float(((uint32_t)u16[i]) << 16);
        bf_ok = bf_ok && isfinite(v) && (v > 1e-4f) && (v < 0.5f);
    }
    bool f32_ok = true;
    const float* f = (const float*)s_w;
#pragma unroll
    for (int i = 0; i < 8; ++i) {
        float v = f[i];
        f32_ok = f32_ok && isfinite(v) && (v > 1e-4f) && (v < 0.5f);
    }
    g_sw_mode = bf_ok ? 2 : (f32_ok ? 1 : 0);

    const int* pi = (const int*)pw;
    bool i32_ok = true;
#pragma unroll
    for (int i = 0; i < 64; ++i) { int v = pi[i]; i32_ok = i32_ok && (v >= 0) && (v <= 255); }
    g_pw_is_i32 = i32_ok ? 1 : 0;
}

// ============================================================================
// Kernel 1: per-column 0.999 quantile of |x| -> s_a (and 1/s_a)
// ============================================================================
__global__ void quantile_kernel(const float* __restrict__ x) {
    __shared__ float tops[256][10];
    const int t = threadIdx.x, cl = t & 63, chunk = t >> 6;
    const int col = blockIdx.x * 64 + cl;
    const float* p = x + (size_t)chunk * 2048 * IN_F + col;

    float tt[10];
#pragma unroll
    for (int i = 0; i < 10; ++i) tt[i] = -1.0f;
#pragma unroll 4
    for (int r = 0; r < 2048; ++r) {
        float v = fabsf(p[(size_t)r * IN_F]);
        if (v > tt[9]) {
            tt[9] = v;
#pragma unroll
            for (int j = 9; j > 0; --j)
                if (tt[j] > tt[j - 1]) { float tmp = tt[j - 1]; tt[j - 1] = tt[j]; tt[j] = tmp; }
        }
    }
#pragma unroll
    for (int i = 0; i < 10; ++i) tops[t][i] = tt[i];
    __syncthreads();

    if (chunk == 0) {
        int pi[4] = {0, 0, 0, 0};
        float v9th = 0.f, v10th = 0.f;
        for (int i = 0; i < 10; ++i) {
            int best = 0; float bv = tops[cl][pi[0]];
#pragma unroll
            for (int j = 1; j < 4; ++j) {
                float c = tops[cl + 64 * j][pi[j]];
                if (c > bv) { bv = c; best = j; }
            }
            pi[best]++;
            if (i == 8) v9th = bv;
            if (i == 9) v10th = bv;
        }
        float pos = 0.999f * 8191.0f;
        float qv  = v10th * (8183.0f - pos) + v9th * (pos - 8182.0f);
        float s = fmaxf(qv, 1e-6f) / 127.0f;
        s = fmaxf(s, 1e-6f);
        s = __half2float(__float2half_rn(s));
        g_sa[col]  = s;
        g_rsa[col] = 1.0f / s;
    }
}

// ============================================================================
// Kernel 2: fake-quant x -> fp16 x_deq (8 elem/thread, reciprocal multiply)
// ============================================================================
__global__ void quant_x_kernel(const float* __restrict__ x) {
    size_t i = (size_t)blockIdx.x * blockDim.x + threadIdx.x;
    size_t base = i * 8;
    int kb = (int)(base & (IN_F - 1));

    const float4* xp = (const float4*)(x + base);
    float4 x0 = xp[0], x1 = xp[1];
    const float4* sp = (const float4*)(g_sa + kb);
    float4 s0 = sp[0], s1 = sp[1];
    const float4* rp = (const float4*)(g_rsa + kb);
    float4 r0 = rp[0], r1 = rp[1];

    float xs[8] = {x0.x, x0.y, x0.z, x0.w, x1.x, x1.y, x1.z, x1.w};
    float ss[8] = {s0.x, s0.y, s0.z, s0.w, s1.x, s1.y, s1.z, s1.w};
    float rs[8] = {r0.x, r0.y, r0.z, r0.w, r1.x, r1.y, r1.z, r1.w};

    union { __half2 h2[4]; uint4 u; } pk;
#pragma unroll
    for (int j = 0; j < 8; j += 2) {
        float q0 = fminf(fmaxf(rintf(xs[j]     * rs[j]),     -127.f), 127.f);
        float q1 = fminf(fmaxf(rintf(xs[j + 1] * rs[j + 1]), -127.f), 127.f);
        pk.h2[j >> 1] = __halves2half2(__float2half_rn(q0 * ss[j]),
                                       __float2half_rn(q1 * ss[j + 1]));
    }
    reinterpret_cast<uint4*>(g_xdeq)[i] = pk.u;
}

// ============================================================================
// Kernel 3: int4 unpack + scale -> fp16 w_deq (8 packed bytes/thread)
// ============================================================================
__global__ void dequant_w_kernel(const void* __restrict__ pw,
                                 const void* __restrict__ s_w) {
    size_t i = (size_t)blockIdx.x * blockDim.x + threadIdx.x;
    int b8[8];
    if (g_pw_is_i32) {
        const int4* p = (const int4*)pw + i * 2;
        int4 a = p[0], b = p[1];
        b8[0] = a.x & 0xFF; b8[1] = a.y & 0xFF; b8[2] = a.z & 0xFF; b8[3] = a.w & 0xFF;
        b8[4] = b.x & 0xFF; b8[5] = b.y & 0xFF; b8[6] = b.z & 0xFF; b8[7] = b.w & 0xFF;
    } else {
        uint2 w = reinterpret_cast<const uint2*>(pw)[i];
#pragma unroll
        for (int j = 0; j < 4; ++j) { b8[j] = (w.x >> (8 * j)) & 0xFF; b8[4 + j] = (w.y >> (8 * j)) & 0xFF; }
    }
    int o = (int)(i >> 8);
    float sw;
    int mode = g_sw_mode;
    if (mode == 1)      sw = ((const float*)s_w)[o];
    else if (mode == 2) sw = __uint_as_float(((uint32_t)((const uint16_t*)s_w)[o]) << 16);
    else                sw = __half2float(((const __half*)s_w)[o]);

    union { __half2 h2[8]; uint4 u[2]; } pk;
#pragma unroll
    for (int j = 0; j < 8; ++j) {
        int b  = b8[j];
        int lo = ((b & 15) ^ 8) - 8;
        int hi = ((b >> 4) ^ 8) - 8;
        pk.h2[j] = __halves2half2(__float2half_rn((float)lo * sw),
                                  __float2half_rn((float)hi * sw));
    }
    uint4* dst = reinterpret_cast<uint4*>(g_wdeq) + i * 2;
    dst[0] = pk.u[0];
    dst[1] = pk.u[1];
}

// ============================================================================
// Kernel 4: GEMM  out[8192,11008] = x_deq @ w_deq^T + bias
//   EXACT round-3 structure (measured 99% of legacy-HMMA rt=16 ceiling).
// ============================================================================
#define GBM 128
#define GBN 128
#define GBK 32
#define GST 40

__global__ void __launch_bounds__(256)
gemm_kernel(const float* __restrict__ bias, float* __restrict__ out) {
    __shared__ __align__(16) __half As[2][GBM * GST];
    __shared__ __align__(16) __half Bs[2][GBN * GST];

    const int bn = blockIdx.x, bm = blockIdx.y;
    const int tid  = threadIdx.x;
    const int warp = tid >> 5, lane = tid & 31;
    const int wm = warp >> 2, wn = warp & 3;

    const __half* Ag = g_xdeq + (size_t)(bm * GBM) * IN_F;
    const __half* Bg = g_wdeq + (size_t)(bn * GBN) * IN_F;

    const uint32_t as_base = (uint32_t)__cvta_generic_to_shared(&As[0][0]);
    const uint32_t bs_base = (uint32_t)__cvta_generic_to_shared(&Bs[0][0]);

    float acc[4][4][4];
#pragma unroll
    for (int mt = 0; mt < 4; ++mt)
#pragma unroll
        for (int nt = 0; nt < 4; ++nt)
#pragma unroll
            for (int r = 0; r < 4; ++r) acc[mt][nt][r] = 0.f;

    auto load_tile = [&](int kt, int buf) {
#pragma unroll
        for (int h = 0; h < 2; ++h) {
            int c    = tid + h * 256;
            int row  = c >> 2;
            int col8 = (c & 3) * 8;
            const __half* ga = Ag + (size_t)row * IN_F + kt * GBK + col8;
            uint32_t sa = as_base + (uint32_t)(buf * GBM * GST + row * GST + col8) * 2u;
            asm volatile("cp.async.cg.shared.global [%0], [%1], 16;\n" :: "r"(sa), "l"(ga));
            const __half* gb = Bg + (size_t)row * IN_F + kt * GBK + col8;
            uint32_t sb = bs_base + (uint32_t)(buf * GBN * GST + row * GST + col8) * 2u;
            asm volatile("cp.async.cg.shared.global [%0], [%1], 16;\n" :: "r"(sb), "l"(gb));
        }
    };

    auto compute = [&](int buf) {
        const int g   = lane >> 3;
        const int idx = lane & 7;
#pragma unroll
        for (int kk = 0; kk < GBK; kk += 16) {
            uint32_t a[4][4];
#pragma unroll
            for (int mt = 0; mt < 4; ++mt) {
                int row = wm * 64 + mt * 16 + idx + (g & 1) * 8;
                int col = kk + (g >> 1) * 8;
                uint32_t addr = as_base + (uint32_t)(buf * GBM * GST + row * GST + col) * 2u;
                asm volatile("ldmatrix.sync.aligned.m8n8.x4.shared.b16 {%0,%1,%2,%3}, [%4];\n"
                             : "=r"(a[mt][0]), "=r"(a[mt][1]), "=r"(a[mt][2]), "=r"(a[mt][3])
                             : "r"(addr));
            }
            uint32_t b[2][4];
#pragma unroll
            for (int bt = 0; bt < 2; ++bt) {
                int n   = wn * 32 + bt * 16 + idx + (g >> 1) * 8;
                int col = kk + (g & 1) * 8;
                uint32_t addr = bs_base + (uint32_t)(buf * GBN * GST + n * GST + col) * 2u;
                asm volatile("ldmatrix.sync.aligned.m8n8.x4.shared.b16 {%0,%1,%2,%3}, [%4];\n"
                             : "=r"(b[bt][0]), "=r"(b[bt][1]), "=r"(b[bt][2]), "=r"(b[bt][3])
                             : "r"(addr));
            }
#pragma unroll
            for (int mt = 0; mt < 4; ++mt) {
#pragma unroll
                for (int nt = 0; nt < 4; ++nt) {
                    uint32_t b0 = b[nt >> 1][(nt & 1) * 2];
                    uint32_t b1 = b[nt >> 1][(nt & 1) * 2 + 1];
                    asm volatile(
                        "mma.sync.aligned.m16n8k16.row.col.f32.f16.f16.f32 "
                        "{%0,%1,%2,%3}, {%4,%5,%6,%7}, {%8,%9}, {%0,%1,%2,%3};\n"
                        : "+f"(acc[mt][nt][0]), "+f"(acc[mt][nt][1]),
                          "+f"(acc[mt][nt][2]), "+f"(acc[mt][nt][3])
                        : "r"(a[mt][0]), "r"(a[mt][1]), "r"(a[mt][2]), "r"(a[mt][3]),
                          "r"(b0), "r"(b1));
                }
            }
        }
    };

    const int NT = IN_F / GBK;   // 128
    load_tile(0, 0);
    asm volatile("cp.async.commit_group;\n");
    asm volatile("cp.async.wait_group 0;\n");
    __syncthreads();

    for (int kt = 0; kt < NT; ++kt) {
        int cur = kt & 1;
        if (kt + 1 < NT) {
            load_tile(kt + 1, cur ^ 1);
            asm volatile("cp.async.commit_group;\n");
        }
        compute(cur);
        if (kt + 1 < NT) asm volatile("cp.async.wait_group 0;\n");
        __syncthreads();
    }

#pragma unroll
    for (int nt = 0; nt < 4; ++nt) {
        int c0 = bn * GBN + wn * 32 + nt * 8 + (lane & 3) * 2;
        float b0 = bias[c0], b1 = bias[c0 + 1];
#pragma unroll
        for (int mt = 0; mt < 4; ++mt) {
            int r0 = bm * GBM + wm * 64 + mt * 16 + (lane >> 2);
            float2 v0 = make_float2(acc[mt][nt][0] + b0, acc[mt][nt][1] + b1);
            float2 v1 = make_float2(acc[mt][nt][2] + b0, acc[mt][nt][3] + b1);
            *reinterpret_cast<float2*>(out + (size_t)r0 * OUT_F + c0)       = v0;
            *reinterpret_cast<float2*>(out + (size_t)(r0 + 8) * OUT_F + c0) = v1;
        }
    }
}

// ============================================================================
// launch — prep DAG overlapped via capture-safe stream fork:
//   main:  detect -> quantile -> quant_x ----------\
//   side:         \-> dequant_w (indep of quantile) -> join -> gemm
// ============================================================================
extern "C" void kernel_launch(void* const* d_in, const int* in_sizes, int n_in,
                              void* d_out, int out_size) {
    const float* x    = (const float*)d_in[0];
    const void*  pw   = (const void*)d_in[1];
    const void*  s_w  = (const void*)d_in[2];
    const float* bias = (const float*)d_in[3];
    float*       out  = (float*)d_out;

    static cudaStream_t s2 = nullptr;
    static cudaEvent_t  e_fork = nullptr, e_join = nullptr;
    if (s2 == nullptr) {
        cudaStreamCreateWithFlags(&s2, cudaStreamNonBlocking);
        cudaEventCreateWithFlags(&e_fork, cudaEventDisableTiming);
        cudaEventCreateWithFlags(&e_join, cudaEventDisableTiming);
    }

    detect_kernel<<<1, 1>>>(s_w, pw);
    cudaEventRecord(e_fork, 0);                      // fork point (after detect)
    cudaStreamWaitEvent(s2, e_fork, 0);
    dequant_w_kernel<<<(OUT_F * (IN_F / 2) / 8) / 256, 256, 0, s2>>>(pw, s_w);
    cudaEventRecord(e_join, s2);

    quantile_kernel<<<IN_F / 64, 256>>>(x);
    quant_x_kernel<<<(TOKENS * IN_F / 8) / 256, 256>>>(x);

    cudaStreamWaitEvent(0, e_join, 0);               // join before GEMM
    gemm_kernel<<<dim3(OUT_F / GBN, TOKENS / GBM), 256>>>(bias, out);
}

// round 17
// speedup vs baseline: 1.7373x; 1.0999x over previous
#include <cuda_runtime.h>
#include <cuda_fp16.h>
#include <stdint.h>

#define TOKENS 8192
#define IN_F   4096
#define OUT_F  11008

// ---------------- scratch (device globals; no allocation allowed) -----------
__device__ __align__(16) float  g_sa[IN_F];
__device__ __align__(16) float  g_rsa[IN_F];
__device__ __align__(16) __half g_xdeq[(size_t)TOKENS * IN_F];   // 64 MB
__device__ __align__(16) __half g_wdeq[(size_t)OUT_F  * IN_F];   // 88 MB
__device__ int g_sw_mode;
__device__ int g_pw_is_i32;

// ============================================================================
// Kernel 0: input dtype detection
// ============================================================================
__global__ void detect_kernel(const void* __restrict__ s_w, const void* __restrict__ pw) {
    bool bf_ok = true;
    const uint16_t* u16 = (const uint16_t*)s_w;
#pragma unroll
    for (int i = 0; i < 16; ++i) {
        float v = __uint_as_float(((uint32_t)u16[i]) << 16);
        bf_ok = bf_ok && isfinite(v) && (v > 1e-4f) && (v < 0.5f);
    }
    bool f32_ok = true;
    const float* f = (const float*)s_w;
#pragma unroll
    for (int i = 0; i < 8; ++i) {
        float v = f[i];
        f32_ok = f32_ok && isfinite(v) && (v > 1e-4f) && (v < 0.5f);
    }
    g_sw_mode = bf_ok ? 2 : (f32_ok ? 1 : 0);

    const int* pi = (const int*)pw;
    bool i32_ok = true;
#pragma unroll
    for (int i = 0; i < 64; ++i) { int v = pi[i]; i32_ok = i32_ok && (v >= 0) && (v <= 255); }
    g_pw_is_i32 = i32_ok ? 1 : 0;
}

// ============================================================================
// Kernel 1: per-column 0.999 quantile of |x| -> s_a (and 1/s_a)
// ============================================================================
__global__ void quantile_kernel(const float* __restrict__ x) {
    __shared__ float tops[256][10];
    const int t = threadIdx.x, cl = t & 63, chunk = t >> 6;
    const int col = blockIdx.x * 64 + cl;
    const float* p = x + (size_t)chunk * 2048 * IN_F + col;

    float tt[10];
#pragma unroll
    for (int i = 0; i < 10; ++i) tt[i] = -1.0f;
#pragma unroll 4
    for (int r = 0; r < 2048; ++r) {
        float v = fabsf(p[(size_t)r * IN_F]);
        if (v > tt[9]) {
            tt[9] = v;
#pragma unroll
            for (int j = 9; j > 0; --j)
                if (tt[j] > tt[j - 1]) { float tmp = tt[j - 1]; tt[j - 1] = tt[j]; tt[j] = tmp; }
        }
    }
#pragma unroll
    for (int i = 0; i < 10; ++i) tops[t][i] = tt[i];
    __syncthreads();

    if (chunk == 0) {
        int pi[4] = {0, 0, 0, 0};
        float v9th = 0.f, v10th = 0.f;
        for (int i = 0; i < 10; ++i) {
            int best = 0; float bv = tops[cl][pi[0]];
#pragma unroll
            for (int j = 1; j < 4; ++j) {
                float c = tops[cl + 64 * j][pi[j]];
                if (c > bv) { bv = c; best = j; }
            }
            pi[best]++;
            if (i == 8) v9th = bv;
            if (i == 9) v10th = bv;
        }
        float pos = 0.999f * 8191.0f;
        float qv  = v10th * (8183.0f - pos) + v9th * (pos - 8182.0f);
        float s = fmaxf(qv, 1e-6f) / 127.0f;
        s = fmaxf(s, 1e-6f);
        s = __half2float(__float2half_rn(s));
        g_sa[col]  = s;
        g_rsa[col] = 1.0f / s;
    }
}

// ============================================================================
// Kernel 2: fake-quant x -> fp16 x_deq (8 elem/thread, reciprocal multiply)
// ============================================================================
__global__ void quant_x_kernel(const float* __restrict__ x) {
    size_t i = (size_t)blockIdx.x * blockDim.x + threadIdx.x;
    size_t base = i * 8;
    int kb = (int)(base & (IN_F - 1));

    const float4* xp = (const float4*)(x + base);
    float4 x0 = xp[0], x1 = xp[1];
    const float4* sp = (const float4*)(g_sa + kb);
    float4 s0 = sp[0], s1 = sp[1];
    const float4* rp = (const float4*)(g_rsa + kb);
    float4 r0 = rp[0], r1 = rp[1];

    float xs[8] = {x0.x, x0.y, x0.z, x0.w, x1.x, x1.y, x1.z, x1.w};
    float ss[8] = {s0.x, s0.y, s0.z, s0.w, s1.x, s1.y, s1.z, s1.w};
    float rs[8] = {r0.x, r0.y, r0.z, r0.w, r1.x, r1.y, r1.z, r1.w};

    union { __half2 h2[4]; uint4 u; } pk;
#pragma unroll
    for (int j = 0; j < 8; j += 2) {
        float q0 = fminf(fmaxf(rintf(xs[j]     * rs[j]),     -127.f), 127.f);
        float q1 = fminf(fmaxf(rintf(xs[j + 1] * rs[j + 1]), -127.f), 127.f);
        pk.h2[j >> 1] = __halves2half2(__float2half_rn(q0 * ss[j]),
                                       __float2half_rn(q1 * ss[j + 1]));
    }
    reinterpret_cast<uint4*>(g_xdeq)[i] = pk.u;
}

// ============================================================================
// Kernel 3: int4 unpack + scale -> fp16 w_deq (8 packed bytes/thread)
// ============================================================================
__global__ void dequant_w_kernel(const void* __restrict__ pw,
                                 const void* __restrict__ s_w) {
    size_t i = (size_t)blockIdx.x * blockDim.x + threadIdx.x;
    int b8[8];
    if (g_pw_is_i32) {
        const int4* p = (const int4*)pw + i * 2;
        int4 a = p[0], b = p[1];
        b8[0] = a.x & 0xFF; b8[1] = a.y & 0xFF; b8[2] = a.z & 0xFF; b8[3] = a.w & 0xFF;
        b8[4] = b.x & 0xFF; b8[5] = b.y & 0xFF; b8[6] = b.z & 0xFF; b8[7] = b.w & 0xFF;
    } else {
        uint2 w = reinterpret_cast<const uint2*>(pw)[i];
#pragma unroll
        for (int j = 0; j < 4; ++j) { b8[j] = (w.x >> (8 * j)) & 0xFF; b8[4 + j] = (w.y >> (8 * j)) & 0xFF; }
    }
    int o = (int)(i >> 8);
    float sw;
    int mode = g_sw_mode;
    if (mode == 1)      sw = ((const float*)s_w)[o];
    else if (mode == 2) sw = __uint_as_float(((uint32_t)((const uint16_t*)s_w)[o]) << 16);
    else                sw = __half2float(((const __half*)s_w)[o]);

    union { __half2 h2[8]; uint4 u[2]; } pk;
#pragma unroll
    for (int j = 0; j < 8; ++j) {
        int b  = b8[j];
        int lo = ((b & 15) ^ 8) - 8;
        int hi = ((b >> 4) ^ 8) - 8;
        pk.h2[j] = __halves2half2(__float2half_rn((float)lo * sw),
                                  __float2half_rn((float)hi * sw));
    }
    uint4* dst = reinterpret_cast<uint4*>(g_wdeq) + i * 2;
    dst[0] = pk.u[0];
    dst[1] = pk.u[1];
}

// ============================================================================
// Kernel 4: GEMM  out[8192,11008] = x_deq @ w_deq^T + bias
//   EXACT round-3 loop; __launch_bounds__(256, 2) -> 128-reg cap, 2 CTAs/SM
//   (40 KB static smem allows it) so sync-point bubbles are filled by the
//   co-resident CTA.
// ============================================================================
#define GBM 128
#define GBN 128
#define GBK 32
#define GST 40

__global__ void __launch_bounds__(256, 2)
gemm_kernel(const float* __restrict__ bias, float* __restrict__ out) {
    __shared__ __align__(16) __half As[2][GBM * GST];
    __shared__ __align__(16) __half Bs[2][GBN * GST];

    const int bn = blockIdx.x, bm = blockIdx.y;
    const int tid  = threadIdx.x;
    const int warp = tid >> 5, lane = tid & 31;
    const int wm = warp >> 2, wn = warp & 3;

    const __half* Ag = g_xdeq + (size_t)(bm * GBM) * IN_F;
    const __half* Bg = g_wdeq + (size_t)(bn * GBN) * IN_F;

    const uint32_t as_base = (uint32_t)__cvta_generic_to_shared(&As[0][0]);
    const uint32_t bs_base = (uint32_t)__cvta_generic_to_shared(&Bs[0][0]);

    float acc[4][4][4];
#pragma unroll
    for (int mt = 0; mt < 4; ++mt)
#pragma unroll
        for (int nt = 0; nt < 4; ++nt)
#pragma unroll
            for (int r = 0; r < 4; ++r) acc[mt][nt][r] = 0.f;

    auto load_tile = [&](int kt, int buf) {
#pragma unroll
        for (int h = 0; h < 2; ++h) {
            int c    = tid + h * 256;
            int row  = c >> 2;
            int col8 = (c & 3) * 8;
            const __half* ga = Ag + (size_t)row * IN_F + kt * GBK + col8;
            uint32_t sa = as_base + (uint32_t)(buf * GBM * GST + row * GST + col8) * 2u;
            asm volatile("cp.async.cg.shared.global [%0], [%1], 16;\n" :: "r"(sa), "l"(ga));
            const __half* gb = Bg + (size_t)row * IN_F + kt * GBK + col8;
            uint32_t sb = bs_base + (uint32_t)(buf * GBN * GST + row * GST + col8) * 2u;
            asm volatile("cp.async.cg.shared.global [%0], [%1], 16;\n" :: "r"(sb), "l"(gb));
        }
    };

    auto compute = [&](int buf) {
        const int g   = lane >> 3;
        const int idx = lane & 7;
#pragma unroll
        for (int kk = 0; kk < GBK; kk += 16) {
            uint32_t a[4][4];
#pragma unroll
            for (int mt = 0; mt < 4; ++mt) {
                int row = wm * 64 + mt * 16 + idx + (g & 1) * 8;
                int col = kk + (g >> 1) * 8;
                uint32_t addr = as_base + (uint32_t)(buf * GBM * GST + row * GST + col) * 2u;
                asm volatile("ldmatrix.sync.aligned.m8n8.x4.shared.b16 {%0,%1,%2,%3}, [%4];\n"
                             : "=r"(a[mt][0]), "=r"(a[mt][1]), "=r"(a[mt][2]), "=r"(a[mt][3])
                             : "r"(addr));
            }
            uint32_t b[2][4];
#pragma unroll
            for (int bt = 0; bt < 2; ++bt) {
                int n   = wn * 32 + bt * 16 + idx + (g >> 1) * 8;
                int col = kk + (g & 1) * 8;
                uint32_t addr = bs_base + (uint32_t)(buf * GBN * GST + n * GST + col) * 2u;
                asm volatile("ldmatrix.sync.aligned.m8n8.x4.shared.b16 {%0,%1,%2,%3}, [%4];\n"
                             : "=r"(b[bt][0]), "=r"(b[bt][1]), "=r"(b[bt][2]), "=r"(b[bt][3])
                             : "r"(addr));
            }
#pragma unroll
            for (int mt = 0; mt < 4; ++mt) {
#pragma unroll
                for (int nt = 0; nt < 4; ++nt) {
                    uint32_t b0 = b[nt >> 1][(nt & 1) * 2];
                    uint32_t b1 = b[nt >> 1][(nt & 1) * 2 + 1];
                    asm volatile(
                        "mma.sync.aligned.m16n8k16.row.col.f32.f16.f16.f32 "
                        "{%0,%1,%2,%3}, {%4,%5,%6,%7}, {%8,%9}, {%0,%1,%2,%3};\n"
                        : "+f"(acc[mt][nt][0]), "+f"(acc[mt][nt][1]),
                          "+f"(acc[mt][nt][2]), "+f"(acc[mt][nt][3])
                        : "r"(a[mt][0]), "r"(a[mt][1]), "r"(a[mt][2]), "r"(a[mt][3]),
                          "r"(b0), "r"(b1));
                }
            }
        }
    };

    const int NT = IN_F / GBK;   // 128
    load_tile(0, 0);
    asm volatile("cp.async.commit_group;\n");
    asm volatile("cp.async.wait_group 0;\n");
    __syncthreads();

    for (int kt = 0; kt < NT; ++kt) {
        int cur = kt & 1;
        if (kt + 1 < NT) {
            load_tile(kt + 1, cur ^ 1);
            asm volatile("cp.async.commit_group;\n");
        }
        compute(cur);
        if (kt + 1 < NT) asm volatile("cp.async.wait_group 0;\n");
        __syncthreads();
    }

#pragma unroll
    for (int nt = 0; nt < 4; ++nt) {
        int c0 = bn * GBN + wn * 32 + nt * 8 + (lane & 3) * 2;
        float b0 = bias[c0], b1 = bias[c0 + 1];
#pragma unroll
        for (int mt = 0; mt < 4; ++mt) {
            int r0 = bm * GBM + wm * 64 + mt * 16 + (lane >> 2);
            float2 v0 = make_float2(acc[mt][nt][0] + b0, acc[mt][nt][1] + b1);
            float2 v1 = make_float2(acc[mt][nt][2] + b0, acc[mt][nt][3] + b1);
            *reinterpret_cast<float2*>(out + (size_t)r0 * OUT_F + c0)       = v0;
            *reinterpret_cast<float2*>(out + (size_t)(r0 + 8) * OUT_F + c0) = v1;
        }
    }
}

// ============================================================================
// launch (flat serial — round-16 stream fork regressed, reverted)
// ============================================================================
extern "C" void kernel_launch(void* const* d_in, const int* in_sizes, int n_in,
                              void* d_out, int out_size) {
    const float* x    = (const float*)d_in[0];
    const void*  pw   = (const void*)d_in[1];
    const void*  s_w  = (const void*)d_in[2];
    const float* bias = (const float*)d_in[3];
    float*       out  = (float*)d_out;

    detect_kernel<<<1, 1>>>(s_w, pw);
    quantile_kernel<<<IN_F / 64, 256>>>(x);
    quant_x_kernel<<<(TOKENS * IN_F / 8) / 256, 256>>>(x);
    dequant_w_kernel<<<(OUT_F * (IN_F / 2) / 8) / 256, 256>>>(pw, s_w);
    gemm_kernel<<<dim3(OUT_F / GBN, TOKENS / GBM), 256>>>(bias, out);
}